// round 14
// baseline (speedup 1.0000x reference)
#include <cuda_runtime.h>
#include <cuda_bf16.h>
#include <stdint.h>
#include <math.h>

#define NH 16
#define DM 1024
#define BB 2
#define SQ 2048
#define SP 2048
#define KTOT 4096
#define CAP 512

#define OUT_PRES 4194304
#define OUT_ATTN 12582912

// ---------------- scratch (device globals; no allocation) ----------------
__device__ float g_Q[(size_t)BB * NH * SQ * 64];      // 16 MB
__device__ float g_SA[(size_t)BB * SQ * DM];          // 16 MB raw-reshape layout
__device__ __nv_bfloat16 g_Xhi[(size_t)4096 * 1024];
__device__ __nv_bfloat16 g_Xlo[(size_t)4096 * 1024];
__device__ __nv_bfloat16 g_W1hi[(size_t)3072 * 1024];  // [N][K] K-major
__device__ __nv_bfloat16 g_W1lo[(size_t)3072 * 1024];
__device__ __nv_bfloat16 g_W2hi[(size_t)1024 * 1024];
__device__ __nv_bfloat16 g_W2lo[(size_t)1024 * 1024];
__device__ __nv_bfloat16 g_SAhi[(size_t)4096 * 1024];
__device__ __nv_bfloat16 g_SAlo[(size_t)4096 * 1024];
__device__ int   g_cnt[SQ];
__device__ int   g_cand[SQ * CAP];
__device__ unsigned g_qmax2;
__device__ unsigned g_kmax2;

__global__ void init_kernel() { g_qmax2 = 0u; g_kmax2 = 0u; }

// ---------------- helpers (base-PTX only: sm_80/90 features) -------------
__device__ __forceinline__ uint32_t smem_u32(const void* p) {
    uint32_t a;
    asm("{ .reg .u64 t; cvta.to.shared.u64 t, %1; cvt.u32.u64 %0, t; }" : "=r"(a) : "l"(p));
    return a;
}
__device__ __forceinline__ void cp16(uint32_t dst, const void* src) {
    asm volatile("cp.async.cg.shared.global [%0], [%1], 16;" :: "r"(dst), "l"(src));
}

// ---------------- split kernels ------------------------------------------
__global__ void split_kernel(const float* __restrict__ src,
                             __nv_bfloat16* __restrict__ hi,
                             __nv_bfloat16* __restrict__ lo) {
    const size_t i = ((size_t)blockIdx.x * blockDim.x + threadIdx.x) * 4;
    float4 v = *(const float4*)(src + i);
    __nv_bfloat16 h0 = __float2bfloat16_rn(v.x), h1 = __float2bfloat16_rn(v.y);
    __nv_bfloat16 h2 = __float2bfloat16_rn(v.z), h3 = __float2bfloat16_rn(v.w);
    __nv_bfloat162* H = (__nv_bfloat162*)(hi + i);
    H[0] = __nv_bfloat162(h0, h1); H[1] = __nv_bfloat162(h2, h3);
    __nv_bfloat162* L = (__nv_bfloat162*)(lo + i);
    L[0] = __nv_bfloat162(__float2bfloat16_rn(v.x - __bfloat162float(h0)),
                          __float2bfloat16_rn(v.y - __bfloat162float(h1)));
    L[1] = __nv_bfloat162(__float2bfloat16_rn(v.z - __bfloat162float(h2)),
                          __float2bfloat16_rn(v.w - __bfloat162float(h3)));
}

// W [K][N] fp32 -> hi/lo [N][K] bf16 (transpose + split)
__global__ void splitT_kernel(const float* __restrict__ W,
                              __nv_bfloat16* __restrict__ hi,
                              __nv_bfloat16* __restrict__ lo, int K, int N) {
    __shared__ float t[32][33];
    const int k0 = blockIdx.y * 32, n0 = blockIdx.x * 32;
    const int tx = threadIdx.x, ty = threadIdx.y;
#pragma unroll
    for (int r = 0; r < 4; r++)
        t[ty * 4 + r][tx] = W[(size_t)(k0 + ty * 4 + r) * N + n0 + tx];
    __syncthreads();
#pragma unroll
    for (int r = 0; r < 4; r++) {
        float v = t[tx][ty * 4 + r];
        __nv_bfloat16 h = __float2bfloat16_rn(v);
        size_t o = (size_t)(n0 + ty * 4 + r) * K + k0 + tx;
        hi[o] = h;
        lo[o] = __float2bfloat16_rn(v - __bfloat162float(h));
    }
}

// ---------------- mma.sync GEMM ------------------------------------------
// D[m][n] = sum_{k'=0..3071} A'[m][k'] * B'[n][k'] + bias[n]
// phases: 0 hi*hi, 1 lo*hi, 2 hi*lo.  MODE 0: QKV scatter, MODE 1: out.
#define BKT 32
#define STAGES 3
#define ROWB 80                       // 64B data + 16B pad: conflict-free ldmatrix
#define STAGE_BYTES (2 * 128 * ROWB)  // 20480

template <int MODE>
__device__ __forceinline__ void store2(int m, int n, float v0, float v1,
                                       float* outp, float* pres) {
    float2 val = make_float2(v0, v1);
    if (MODE == 1) {
        *(float2*)(outp + (size_t)m * 1024 + n) = val;
    } else {
        const int b = m >> 11, sidx = m & 2047;
        if (n < DM) {
            const int h = n >> 6, dd = n & 63;
            *(float2*)(g_Q + (((size_t)(b * NH + h) * SQ + sidx) << 6) + dd) = val;
        } else if (n < 2 * DM) {
            const int nn = n - DM, h = nn >> 6, dd = nn & 63;
            *(float2*)(pres + (((size_t)((b * 2 + 0) * NH + h) * SQ + sidx) << 6) + dd) = val;
        } else {
            const int nn = n - 2 * DM, h = nn >> 6, dd = nn & 63;
            *(float2*)(pres + (((size_t)((b * 2 + 1) * NH + h) * SQ + sidx) << 6) + dd) = val;
        }
    }
}

template <int MODE>
__global__ void __launch_bounds__(256) gemm_mma(
    const __nv_bfloat16* __restrict__ Ahi, const __nv_bfloat16* __restrict__ Alo,
    const __nv_bfloat16* __restrict__ Bhi, const __nv_bfloat16* __restrict__ Blo,
    const float* __restrict__ bias, float* __restrict__ outp,
    float* __restrict__ pres)
{
    extern __shared__ char smc[];
    const uint32_t sbase = smem_u32(smc);
    const int tid = threadIdx.x;
    const int lane = tid & 31, wid = tid >> 5;
    const int wm = wid & 1, wn = wid >> 1;  // 2x4 warp grid: 64x32 per warp
    const int m0 = blockIdx.y * 128, n0 = blockIdx.x * 128;

    float d[4][4][4];
#pragma unroll
    for (int i = 0; i < 4; i++)
#pragma unroll
        for (int j = 0; j < 4; j++)
#pragma unroll
            for (int r = 0; r < 4; r++) d[i][j][r] = 0.f;

    const int lr = tid >> 2, lseg = tid & 3;  // load task split: 64 rows/wave

    // stage loader: A rows m0..m0+127, B rows n0..n0+127, 32 k each
#define LOAD_STAGE(kt)                                                          \
    do {                                                                        \
        const int _phase = (kt) >> 5;                                           \
        const int _kl = ((kt) & 31) * BKT;                                      \
        const __nv_bfloat16* _As = (_phase == 1) ? Alo : Ahi;                   \
        const __nv_bfloat16* _Bs = (_phase == 2) ? Blo : Bhi;                   \
        const int _s = (kt) % STAGES;                                           \
        const uint32_t _ab = sbase + _s * STAGE_BYTES;                          \
        const uint32_t _bb = _ab + 128 * ROWB;                                  \
        cp16(_ab + lr * ROWB + lseg * 16,                                       \
             _As + (size_t)(m0 + lr) * 1024 + _kl + lseg * 8);                  \
        cp16(_ab + (lr + 64) * ROWB + lseg * 16,                                \
             _As + (size_t)(m0 + lr + 64) * 1024 + _kl + lseg * 8);             \
        cp16(_bb + lr * ROWB + lseg * 16,                                       \
             _Bs + (size_t)(n0 + lr) * 1024 + _kl + lseg * 8);                  \
        cp16(_bb + (lr + 64) * ROWB + lseg * 16,                                \
             _Bs + (size_t)(n0 + lr + 64) * 1024 + _kl + lseg * 8);             \
        asm volatile("cp.async.commit_group;");                                 \
    } while (0)

    LOAD_STAGE(0);
    LOAD_STAGE(1);

    for (int kt = 0; kt < 96; kt++) {
        asm volatile("cp.async.wait_group 1;");
        __syncthreads();
        if (kt + 2 < 96) LOAD_STAGE(kt + 2);
        const int s = kt % STAGES;
        const uint32_t abase = sbase + s * STAGE_BYTES;
        const uint32_t bbase = abase + 128 * ROWB;
#pragma unroll
        for (int step = 0; step < 2; step++) {
            uint32_t a[4][4], b[4][2];
#pragma unroll
            for (int im = 0; im < 4; im++) {
                uint32_t addr = abase + (wm * 64 + im * 16 + (lane & 15)) * ROWB
                              + (step * 2 + (lane >> 4)) * 16;
                asm volatile(
                    "ldmatrix.sync.aligned.m8n8.x4.shared.b16 {%0,%1,%2,%3}, [%4];"
                    : "=r"(a[im][0]), "=r"(a[im][1]), "=r"(a[im][2]), "=r"(a[im][3])
                    : "r"(addr));
            }
#pragma unroll
            for (int jn = 0; jn < 4; jn++) {
                uint32_t addr = bbase + (wn * 32 + jn * 8 + (lane & 7)) * ROWB
                              + (step * 2 + ((lane >> 3) & 1)) * 16;
                asm volatile(
                    "ldmatrix.sync.aligned.m8n8.x2.shared.b16 {%0,%1}, [%2];"
                    : "=r"(b[jn][0]), "=r"(b[jn][1]) : "r"(addr));
            }
#pragma unroll
            for (int im = 0; im < 4; im++)
#pragma unroll
                for (int jn = 0; jn < 4; jn++)
                    asm volatile(
                        "mma.sync.aligned.m16n8k16.row.col.f32.bf16.bf16.f32 "
                        "{%0,%1,%2,%3}, {%4,%5,%6,%7}, {%8,%9}, {%0,%1,%2,%3};"
                        : "+f"(d[im][jn][0]), "+f"(d[im][jn][1]),
                          "+f"(d[im][jn][2]), "+f"(d[im][jn][3])
                        : "r"(a[im][0]), "r"(a[im][1]), "r"(a[im][2]), "r"(a[im][3]),
                          "r"(b[jn][0]), "r"(b[jn][1]));
        }
    }

    // epilogue: c0,c1 -> row (lane>>2), c2,c3 -> row +8; cols 2*(lane&3)+{0,1}
#pragma unroll
    for (int im = 0; im < 4; im++) {
        const int mlo = m0 + wm * 64 + im * 16 + (lane >> 2);
#pragma unroll
        for (int jn = 0; jn < 4; jn++) {
            const int n = n0 + wn * 32 + jn * 8 + (lane & 3) * 2;
            const float bv0 = bias[n], bv1 = bias[n + 1];
            store2<MODE>(mlo,     n, d[im][jn][0] + bv0, d[im][jn][1] + bv1, outp, pres);
            store2<MODE>(mlo + 8, n, d[im][jn][2] + bv0, d[im][jn][3] + bv1, outp, pres);
        }
    }
#undef LOAD_STAGE
}

// ---------------- row-norm maxima ----------------------------------------
__global__ void qnorm_kernel() {
    const int warp = (blockIdx.x * blockDim.x + threadIdx.x) >> 5;
    const int lane = threadIdx.x & 31;
    const float* p = g_Q + (size_t)warp * 64;
    float x0 = p[2 * lane], x1 = p[2 * lane + 1];
    float ss = x0 * x0 + x1 * x1;
#pragma unroll
    for (int o = 16; o; o >>= 1) ss += __shfl_xor_sync(0xffffffffu, ss, o);
    __shared__ float red[8];
    if (lane == 0) red[threadIdx.x >> 5] = ss;
    __syncthreads();
    if (threadIdx.x == 0) {
        float mx = red[0];
#pragma unroll
        for (int i = 1; i < 8; i++) mx = fmaxf(mx, red[i]);
        atomicMax(&g_qmax2, __float_as_uint(mx));
    }
}

__global__ void knorm_kernel(const float* __restrict__ base) {
    const int warp = (blockIdx.x * blockDim.x + threadIdx.x) >> 5;
    const int lane = threadIdx.x & 31;
    const int b = warp >> 15;
    const float* p = base + ((size_t)warp + (size_t)b * 32768) * 64;
    float x0 = p[2 * lane], x1 = p[2 * lane + 1];
    float ss = x0 * x0 + x1 * x1;
#pragma unroll
    for (int o = 16; o; o >>= 1) ss += __shfl_xor_sync(0xffffffffu, ss, o);
    __shared__ float red[8];
    if (lane == 0) red[threadIdx.x >> 5] = ss;
    __syncthreads();
    if (threadIdx.x == 0) {
        float mx = red[0];
#pragma unroll
        for (int i = 1; i < 8; i++) mx = fmaxf(mx, red[i]);
        atomicMax(&g_kmax2, __float_as_uint(mx));
    }
}

// ---------------- mask min + candidates (merged) -------------------------
__global__ void cand_kernel(const float* __restrict__ mask) {
    const int q = blockIdx.x;
    const int tid = threadIdx.x;
    __shared__ float red[256];
    __shared__ float s_thr;
    __shared__ int scnt;
    float mn = 3.4e38f;
    for (int t = tid; t < KTOT; t += 256) mn = fminf(mn, mask[(size_t)q * KTOT + t]);
    red[tid] = mn;
    __syncthreads();
    for (int s = 128; s; s >>= 1) {
        if (tid < s) red[tid] = fminf(red[tid], red[tid + s]);
        __syncthreads();
    }
    if (tid == 0) {
        const float Bq = sqrtf(__uint_as_float(g_qmax2));
        const float Bk = sqrtf(__uint_as_float(g_kmax2));
        const float tau = (2.f * Bq * Bk * 0.125f * 1.02f + 140.f) * 1e-9f;
        s_thr = red[0] + tau;
        scnt = 0;
    }
    __syncthreads();
    const float thr = s_thr;
    for (int t = tid; t < KTOT; t += 256) {
        if (mask[(size_t)q * KTOT + t] <= thr) {
            int p = atomicAdd(&scnt, 1);
            if (p < CAP) g_cand[q * CAP + p] = t;
        }
    }
    __syncthreads();
    if (tid == 0) {
        int n = scnt < CAP ? scnt : CAP;
        g_cnt[q] = n;
        int* c = &g_cand[q * CAP];
        for (int i = 1; i < n; i++) {
            int v = c[i], j = i - 1;
            while (j >= 0 && c[j] > v) { c[j + 1] = c[j]; j--; }
            c[j + 1] = v;
        }
    }
}

// ---------------- sparse attention ---------------------------------------
__global__ void attn_kernel(const float* __restrict__ past,
                            const float* __restrict__ pres,
                            const float* __restrict__ mask,
                            float* __restrict__ attn)
{
    const int row  = (blockIdx.x * blockDim.x + threadIdx.x) >> 5;
    const int lane = threadIdx.x & 31;
    const int w    = threadIdx.x >> 5;
    const int b = row >> 15, h = (row >> 11) & 15, q = row & (SQ - 1);

    __shared__ float lbuf[8][CAP];

    int nc = g_cnt[q];
    if (nc > CAP) nc = CAP;
    const float* qr = g_Q + (size_t)row * 64;
    const float q0 = qr[2 * lane], q1 = qr[2 * lane + 1];

    for (int c = 0; c < nc; c++) {
        const int k = g_cand[q * CAP + c];
        const float* kr = (k < SP)
            ? past + (((size_t)((b * 2 + 0) * NH + h) * SP + k) << 6)
            : pres + (((size_t)((b * 2 + 0) * NH + h) * SQ + (k - SP)) << 6);
        float part = q0 * kr[2 * lane] + q1 * kr[2 * lane + 1];
#pragma unroll
        for (int o = 16; o; o >>= 1) part += __shfl_xor_sync(0xffffffffu, part, o);
        if (lane == 0)
            lbuf[w][c] = part * 0.125f + mask[(size_t)q * KTOT + k] * (-1000000000.0f);
    }
    __syncwarp();

    float m = -3.4e38f;
    for (int c = 0; c < nc; c++) m = fmaxf(m, lbuf[w][c]);
    float s = 0.f;
    for (int c = 0; c < nc; c++) s += expf(lbuf[w][c] - m);

    float a0 = 0.f, a1 = 0.f;
    for (int c = 0; c < nc; c++) {
        const int k = g_cand[q * CAP + c];
        const float p = expf(lbuf[w][c] - m) / s;
        if (lane == (c & 31)) attn[(size_t)row * KTOT + k] = p;
        const float* vr = (k < SP)
            ? past + (((size_t)((b * 2 + 1) * NH + h) * SP + k) << 6)
            : pres + (((size_t)((b * 2 + 1) * NH + h) * SQ + (k - SP)) << 6);
        a0 = fmaf(p, vr[2 * lane], a0);
        a1 = fmaf(p, vr[2 * lane + 1], a1);
    }
    // raw reshape: concat[b][h*128 + q/16][(q%16)*64 + d]
    float* sa = g_SA + ((size_t)(b * SQ + (h * 128 + (q >> 4))) * DM) + ((q & 15) * 64);
    sa[2 * lane]     = a0;
    sa[2 * lane + 1] = a1;
}

// ---------------- launch -------------------------------------------------
extern "C" void kernel_launch(void* const* d_in, const int* in_sizes, int n_in,
                              void* d_out, int out_size)
{
    const float* X    = (const float*)d_in[0];
    const float* past = (const float*)d_in[1];
    const float* mask = (const float*)d_in[2];
    const float* W1   = (const float*)d_in[3];
    const float* b1   = (const float*)d_in[4];
    const float* W2   = (const float*)d_in[5];
    const float* b2   = (const float*)d_in[6];

    float* out  = (float*)d_out;
    float* pres = out + OUT_PRES;
    float* attn = out + OUT_ATTN;

    cudaFuncSetAttribute(gemm_mma<0>, cudaFuncAttributeMaxDynamicSharedMemorySize,
                         STAGES * STAGE_BYTES);
    cudaFuncSetAttribute(gemm_mma<1>, cudaFuncAttributeMaxDynamicSharedMemorySize,
                         STAGES * STAGE_BYTES);

    __nv_bfloat16 *Xhi, *Xlo, *W1hi, *W1lo, *W2hi, *W2lo, *SAhi, *SAlo;
    cudaGetSymbolAddress((void**)&Xhi, g_Xhi);
    cudaGetSymbolAddress((void**)&Xlo, g_Xlo);
    cudaGetSymbolAddress((void**)&W1hi, g_W1hi);
    cudaGetSymbolAddress((void**)&W1lo, g_W1lo);
    cudaGetSymbolAddress((void**)&W2hi, g_W2hi);
    cudaGetSymbolAddress((void**)&W2lo, g_W2lo);
    cudaGetSymbolAddress((void**)&SAhi, g_SAhi);
    cudaGetSymbolAddress((void**)&SAlo, g_SAlo);
    float* SA;
    cudaGetSymbolAddress((void**)&SA, g_SA);

    init_kernel<<<1, 32>>>();
    cudaMemsetAsync(attn, 0, (size_t)BB * NH * SQ * KTOT * sizeof(float));

    // operand splits
    split_kernel<<<4096, 256>>>(X, Xhi, Xlo);
    splitT_kernel<<<dim3(96, 32), dim3(32, 8)>>>(W1, W1hi, W1lo, 1024, 3072);
    splitT_kernel<<<dim3(32, 32), dim3(32, 8)>>>(W2, W2hi, W2lo, 1024, 1024);

    // QKV projection (bf16x3 on tensor cores) + scatter
    gemm_mma<0><<<dim3(24, 32), 256, STAGES * STAGE_BYTES>>>(
        Xhi, Xlo, W1hi, W1lo, b1, out, pres);

    qnorm_kernel<<<8192, 256>>>();
    knorm_kernel<<<8192, 256>>>(past);
    knorm_kernel<<<8192, 256>>>(pres);
    cand_kernel<<<SQ, 256>>>(mask);

    attn_kernel<<<8192, 256>>>(past, pres, mask, attn);

    // output projection
    split_kernel<<<4096, 256>>>(SA, SAhi, SAlo);
    gemm_mma<1><<<dim3(8, 32), 256, STAGES * STAGE_BYTES>>>(
        SAhi, SAlo, W2hi, W2lo, b2, out, pres);
}

// round 15
// speedup vs baseline: 1.0022x; 1.0022x over previous
#include <cuda_runtime.h>
#include <cuda_bf16.h>
#include <stdint.h>
#include <math.h>

#define NH 16
#define DM 1024
#define BB 2
#define SQ 2048
#define SP 2048
#define KTOT 4096
#define CAP 512

#define OUT_PRES 4194304
#define OUT_ATTN 12582912

// ---------------- scratch (device globals; no allocation) ----------------
__device__ float g_Q[(size_t)BB * NH * SQ * 64];      // 16 MB
__device__ float g_SA[(size_t)BB * SQ * DM];          // 16 MB raw-reshape layout
__device__ __nv_bfloat16 g_Xhi[(size_t)4096 * 1024];
__device__ __nv_bfloat16 g_Xlo[(size_t)4096 * 1024];
__device__ __nv_bfloat16 g_W1hi[(size_t)3072 * 1024];  // [N][K] K-major
__device__ __nv_bfloat16 g_W1lo[(size_t)3072 * 1024];
__device__ __nv_bfloat16 g_W2hi[(size_t)1024 * 1024];
__device__ __nv_bfloat16 g_W2lo[(size_t)1024 * 1024];
__device__ __nv_bfloat16 g_SAhi[(size_t)4096 * 1024];
__device__ __nv_bfloat16 g_SAlo[(size_t)4096 * 1024];
__device__ int   g_cnt[SQ];
__device__ int   g_cand[SQ * CAP];
__device__ unsigned g_qmax2;
__device__ unsigned g_kmax2;

__global__ void init_kernel() { g_qmax2 = 0u; g_kmax2 = 0u; }

// ---------------- helpers (base-PTX only: sm_80/90 features) -------------
__device__ __forceinline__ uint32_t smem_u32(const void* p) {
    uint32_t a;
    asm("{ .reg .u64 t; cvta.to.shared.u64 t, %1; cvt.u32.u64 %0, t; }" : "=r"(a) : "l"(p));
    return a;
}
__device__ __forceinline__ void cp16(uint32_t dst, const void* src) {
    asm volatile("cp.async.cg.shared.global [%0], [%1], 16;" :: "r"(dst), "l"(src));
}

// ---------------- split kernels ------------------------------------------
__global__ void split_kernel(const float* __restrict__ src,
                             __nv_bfloat16* __restrict__ hi,
                             __nv_bfloat16* __restrict__ lo) {
    const size_t i = ((size_t)blockIdx.x * blockDim.x + threadIdx.x) * 4;
    float4 v = *(const float4*)(src + i);
    __nv_bfloat16 h0 = __float2bfloat16_rn(v.x), h1 = __float2bfloat16_rn(v.y);
    __nv_bfloat16 h2 = __float2bfloat16_rn(v.z), h3 = __float2bfloat16_rn(v.w);
    __nv_bfloat162* H = (__nv_bfloat162*)(hi + i);
    H[0] = __nv_bfloat162(h0, h1); H[1] = __nv_bfloat162(h2, h3);
    __nv_bfloat162* L = (__nv_bfloat162*)(lo + i);
    L[0] = __nv_bfloat162(__float2bfloat16_rn(v.x - __bfloat162float(h0)),
                          __float2bfloat16_rn(v.y - __bfloat162float(h1)));
    L[1] = __nv_bfloat162(__float2bfloat16_rn(v.z - __bfloat162float(h2)),
                          __float2bfloat16_rn(v.w - __bfloat162float(h3)));
}

// W [K][N] fp32 -> hi/lo [N][K] bf16 (transpose + split)
__global__ void splitT_kernel(const float* __restrict__ W,
                              __nv_bfloat16* __restrict__ hi,
                              __nv_bfloat16* __restrict__ lo, int K, int N) {
    __shared__ float t[32][33];
    const int k0 = blockIdx.y * 32, n0 = blockIdx.x * 32;
    const int tx = threadIdx.x, ty = threadIdx.y;
#pragma unroll
    for (int r = 0; r < 4; r++)
        t[ty * 4 + r][tx] = W[(size_t)(k0 + ty * 4 + r) * N + n0 + tx];
    __syncthreads();
#pragma unroll
    for (int r = 0; r < 4; r++) {
        float v = t[tx][ty * 4 + r];
        __nv_bfloat16 h = __float2bfloat16_rn(v);
        size_t o = (size_t)(n0 + ty * 4 + r) * K + k0 + tx;
        hi[o] = h;
        lo[o] = __float2bfloat16_rn(v - __bfloat162float(h));
    }
}

// ---------------- mma.sync GEMM ------------------------------------------
// D[m][n] = sum_{k'=0..3071} A'[m][k'] * B'[n][k'] + bias[n]
// phases: 0 hi*hi, 1 lo*hi, 2 hi*lo.  MODE 0: QKV scatter, MODE 1: out.
#define BKT 32
#define STAGES 3
#define ROWB 80                       // 64B data + 16B pad: conflict-free ldmatrix
#define STAGE_BYTES (2 * 128 * ROWB)  // 20480

template <int MODE>
__device__ __forceinline__ void store2(int m, int n, float v0, float v1,
                                       float* outp, float* pres) {
    float2 val = make_float2(v0, v1);
    if (MODE == 1) {
        *(float2*)(outp + (size_t)m * 1024 + n) = val;
    } else {
        const int b = m >> 11, sidx = m & 2047;
        if (n < DM) {
            const int h = n >> 6, dd = n & 63;
            *(float2*)(g_Q + (((size_t)(b * NH + h) * SQ + sidx) << 6) + dd) = val;
        } else if (n < 2 * DM) {
            const int nn = n - DM, h = nn >> 6, dd = nn & 63;
            *(float2*)(pres + (((size_t)((b * 2 + 0) * NH + h) * SQ + sidx) << 6) + dd) = val;
        } else {
            const int nn = n - 2 * DM, h = nn >> 6, dd = nn & 63;
            *(float2*)(pres + (((size_t)((b * 2 + 1) * NH + h) * SQ + sidx) << 6) + dd) = val;
        }
    }
}

template <int MODE>
__global__ void __launch_bounds__(256) gemm_mma(
    const __nv_bfloat16* __restrict__ Ahi, const __nv_bfloat16* __restrict__ Alo,
    const __nv_bfloat16* __restrict__ Bhi, const __nv_bfloat16* __restrict__ Blo,
    const float* __restrict__ bias, float* __restrict__ outp,
    float* __restrict__ pres)
{
    extern __shared__ char smc[];
    const uint32_t sbase = smem_u32(smc);
    const int tid = threadIdx.x;
    const int lane = tid & 31, wid = tid >> 5;
    const int wm = wid & 1, wn = wid >> 1;  // 2x4 warp grid: 64x32 per warp
    const int m0 = blockIdx.y * 128, n0 = blockIdx.x * 128;

    float d[4][4][4];
#pragma unroll
    for (int i = 0; i < 4; i++)
#pragma unroll
        for (int j = 0; j < 4; j++)
#pragma unroll
            for (int r = 0; r < 4; r++) d[i][j][r] = 0.f;

    const int lr = tid >> 2, lseg = tid & 3;  // load task split: 64 rows/wave

    // stage loader: A rows m0..m0+127, B rows n0..n0+127, 32 k each
#define LOAD_STAGE(kt)                                                          \
    do {                                                                        \
        const int _phase = (kt) >> 5;                                           \
        const int _kl = ((kt) & 31) * BKT;                                      \
        const __nv_bfloat16* _As = (_phase == 1) ? Alo : Ahi;                   \
        const __nv_bfloat16* _Bs = (_phase == 2) ? Blo : Bhi;                   \
        const int _s = (kt) % STAGES;                                           \
        const uint32_t _ab = sbase + _s * STAGE_BYTES;                          \
        const uint32_t _bb = _ab + 128 * ROWB;                                  \
        cp16(_ab + lr * ROWB + lseg * 16,                                       \
             _As + (size_t)(m0 + lr) * 1024 + _kl + lseg * 8);                  \
        cp16(_ab + (lr + 64) * ROWB + lseg * 16,                                \
             _As + (size_t)(m0 + lr + 64) * 1024 + _kl + lseg * 8);             \
        cp16(_bb + lr * ROWB + lseg * 16,                                       \
             _Bs + (size_t)(n0 + lr) * 1024 + _kl + lseg * 8);                  \
        cp16(_bb + (lr + 64) * ROWB + lseg * 16,                                \
             _Bs + (size_t)(n0 + lr + 64) * 1024 + _kl + lseg * 8);             \
        asm volatile("cp.async.commit_group;");                                 \
    } while (0)

    LOAD_STAGE(0);
    LOAD_STAGE(1);

    for (int kt = 0; kt < 96; kt++) {
        asm volatile("cp.async.wait_group 1;");
        __syncthreads();
        if (kt + 2 < 96) LOAD_STAGE(kt + 2);
        const int s = kt % STAGES;
        const uint32_t abase = sbase + s * STAGE_BYTES;
        const uint32_t bbase = abase + 128 * ROWB;
#pragma unroll
        for (int step = 0; step < 2; step++) {
            uint32_t a[4][4], b[4][2];
#pragma unroll
            for (int im = 0; im < 4; im++) {
                uint32_t addr = abase + (wm * 64 + im * 16 + (lane & 15)) * ROWB
                              + (step * 2 + (lane >> 4)) * 16;
                asm volatile(
                    "ldmatrix.sync.aligned.m8n8.x4.shared.b16 {%0,%1,%2,%3}, [%4];"
                    : "=r"(a[im][0]), "=r"(a[im][1]), "=r"(a[im][2]), "=r"(a[im][3])
                    : "r"(addr));
            }
#pragma unroll
            for (int jn = 0; jn < 4; jn++) {
                uint32_t addr = bbase + (wn * 32 + jn * 8 + (lane & 7)) * ROWB
                              + (step * 2 + ((lane >> 3) & 1)) * 16;
                asm volatile(
                    "ldmatrix.sync.aligned.m8n8.x2.shared.b16 {%0,%1}, [%2];"
                    : "=r"(b[jn][0]), "=r"(b[jn][1]) : "r"(addr));
            }
#pragma unroll
            for (int im = 0; im < 4; im++)
#pragma unroll
                for (int jn = 0; jn < 4; jn++)
                    asm volatile(
                        "mma.sync.aligned.m16n8k16.row.col.f32.bf16.bf16.f32 "
                        "{%0,%1,%2,%3}, {%4,%5,%6,%7}, {%8,%9}, {%0,%1,%2,%3};"
                        : "+f"(d[im][jn][0]), "+f"(d[im][jn][1]),
                          "+f"(d[im][jn][2]), "+f"(d[im][jn][3])
                        : "r"(a[im][0]), "r"(a[im][1]), "r"(a[im][2]), "r"(a[im][3]),
                          "r"(b[jn][0]), "r"(b[jn][1]));
        }
    }

    // epilogue: c0,c1 -> row (lane>>2), c2,c3 -> row +8; cols 2*(lane&3)+{0,1}
#pragma unroll
    for (int im = 0; im < 4; im++) {
        const int mlo = m0 + wm * 64 + im * 16 + (lane >> 2);
#pragma unroll
        for (int jn = 0; jn < 4; jn++) {
            const int n = n0 + wn * 32 + jn * 8 + (lane & 3) * 2;
            const float bv0 = bias[n], bv1 = bias[n + 1];
            store2<MODE>(mlo,     n, d[im][jn][0] + bv0, d[im][jn][1] + bv1, outp, pres);
            store2<MODE>(mlo + 8, n, d[im][jn][2] + bv0, d[im][jn][3] + bv1, outp, pres);
        }
    }
#undef LOAD_STAGE
}

// ---------------- row-norm maxima ----------------------------------------
__global__ void qnorm_kernel() {
    const int warp = (blockIdx.x * blockDim.x + threadIdx.x) >> 5;
    const int lane = threadIdx.x & 31;
    const float* p = g_Q + (size_t)warp * 64;
    float x0 = p[2 * lane], x1 = p[2 * lane + 1];
    float ss = x0 * x0 + x1 * x1;
#pragma unroll
    for (int o = 16; o; o >>= 1) ss += __shfl_xor_sync(0xffffffffu, ss, o);
    __shared__ float red[8];
    if (lane == 0) red[threadIdx.x >> 5] = ss;
    __syncthreads();
    if (threadIdx.x == 0) {
        float mx = red[0];
#pragma unroll
        for (int i = 1; i < 8; i++) mx = fmaxf(mx, red[i]);
        atomicMax(&g_qmax2, __float_as_uint(mx));
    }
}

__global__ void knorm_kernel(const float* __restrict__ base) {
    const int warp = (blockIdx.x * blockDim.x + threadIdx.x) >> 5;
    const int lane = threadIdx.x & 31;
    const int b = warp >> 15;
    const float* p = base + ((size_t)warp + (size_t)b * 32768) * 64;
    float x0 = p[2 * lane], x1 = p[2 * lane + 1];
    float ss = x0 * x0 + x1 * x1;
#pragma unroll
    for (int o = 16; o; o >>= 1) ss += __shfl_xor_sync(0xffffffffu, ss, o);
    __shared__ float red[8];
    if (lane == 0) red[threadIdx.x >> 5] = ss;
    __syncthreads();
    if (threadIdx.x == 0) {
        float mx = red[0];
#pragma unroll
        for (int i = 1; i < 8; i++) mx = fmaxf(mx, red[i]);
        atomicMax(&g_kmax2, __float_as_uint(mx));
    }
}

// ---------------- mask min + candidates (merged) -------------------------
__global__ void cand_kernel(const float* __restrict__ mask) {
    const int q = blockIdx.x;
    const int tid = threadIdx.x;
    __shared__ float red[256];
    __shared__ float s_thr;
    __shared__ int scnt;
    float mn = 3.4e38f;
    for (int t = tid; t < KTOT; t += 256) mn = fminf(mn, mask[(size_t)q * KTOT + t]);
    red[tid] = mn;
    __syncthreads();
    for (int s = 128; s; s >>= 1) {
        if (tid < s) red[tid] = fminf(red[tid], red[tid + s]);
        __syncthreads();
    }
    if (tid == 0) {
        const float Bq = sqrtf(__uint_as_float(g_qmax2));
        const float Bk = sqrtf(__uint_as_float(g_kmax2));
        const float tau = (2.f * Bq * Bk * 0.125f * 1.02f + 140.f) * 1e-9f;
        s_thr = red[0] + tau;
        scnt = 0;
    }
    __syncthreads();
    const float thr = s_thr;
    for (int t = tid; t < KTOT; t += 256) {
        if (mask[(size_t)q * KTOT + t] <= thr) {
            int p = atomicAdd(&scnt, 1);
            if (p < CAP) g_cand[q * CAP + p] = t;
        }
    }
    __syncthreads();
    if (tid == 0) {
        int n = scnt < CAP ? scnt : CAP;
        g_cnt[q] = n;
        int* c = &g_cand[q * CAP];
        for (int i = 1; i < n; i++) {
            int v = c[i], j = i - 1;
            while (j >= 0 && c[j] > v) { c[j + 1] = c[j]; j--; }
            c[j + 1] = v;
        }
    }
}

// ---------------- sparse attention ---------------------------------------
__global__ void attn_kernel(const float* __restrict__ past,
                            const float* __restrict__ pres,
                            const float* __restrict__ mask,
                            float* __restrict__ attn)
{
    const int row  = (blockIdx.x * blockDim.x + threadIdx.x) >> 5;
    const int lane = threadIdx.x & 31;
    const int w    = threadIdx.x >> 5;
    const int b = row >> 15, h = (row >> 11) & 15, q = row & (SQ - 1);

    __shared__ float lbuf[8][CAP];

    int nc = g_cnt[q];
    if (nc > CAP) nc = CAP;
    const float* qr = g_Q + (size_t)row * 64;
    const float q0 = qr[2 * lane], q1 = qr[2 * lane + 1];

    for (int c = 0; c < nc; c++) {
        const int k = g_cand[q * CAP + c];
        const float* kr = (k < SP)
            ? past + (((size_t)((b * 2 + 0) * NH + h) * SP + k) << 6)
            : pres + (((size_t)((b * 2 + 0) * NH + h) * SQ + (k - SP)) << 6);
        float part = q0 * kr[2 * lane] + q1 * kr[2 * lane + 1];
#pragma unroll
        for (int o = 16; o; o >>= 1) part += __shfl_xor_sync(0xffffffffu, part, o);
        if (lane == 0)
            lbuf[w][c] = part * 0.125f + mask[(size_t)q * KTOT + k] * (-1000000000.0f);
    }
    __syncwarp();

    float m = -3.4e38f;
    for (int c = 0; c < nc; c++) m = fmaxf(m, lbuf[w][c]);
    float s = 0.f;
    for (int c = 0; c < nc; c++) s += expf(lbuf[w][c] - m);

    float a0 = 0.f, a1 = 0.f;
    for (int c = 0; c < nc; c++) {
        const int k = g_cand[q * CAP + c];
        const float p = expf(lbuf[w][c] - m) / s;
        if (lane == (c & 31)) attn[(size_t)row * KTOT + k] = p;
        const float* vr = (k < SP)
            ? past + (((size_t)((b * 2 + 1) * NH + h) * SP + k) << 6)
            : pres + (((size_t)((b * 2 + 1) * NH + h) * SQ + (k - SP)) << 6);
        a0 = fmaf(p, vr[2 * lane], a0);
        a1 = fmaf(p, vr[2 * lane + 1], a1);
    }
    // raw reshape: concat[b][h*128 + q/16][(q%16)*64 + d]
    float* sa = g_SA + ((size_t)(b * SQ + (h * 128 + (q >> 4))) * DM) + ((q & 15) * 64);
    sa[2 * lane]     = a0;
    sa[2 * lane + 1] = a1;
}

// ---------------- launch -------------------------------------------------
extern "C" void kernel_launch(void* const* d_in, const int* in_sizes, int n_in,
                              void* d_out, int out_size)
{
    const float* X    = (const float*)d_in[0];
    const float* past = (const float*)d_in[1];
    const float* mask = (const float*)d_in[2];
    const float* W1   = (const float*)d_in[3];
    const float* b1   = (const float*)d_in[4];
    const float* W2   = (const float*)d_in[5];
    const float* b2   = (const float*)d_in[6];

    float* out  = (float*)d_out;
    float* pres = out + OUT_PRES;
    float* attn = out + OUT_ATTN;

    cudaFuncSetAttribute(gemm_mma<0>, cudaFuncAttributeMaxDynamicSharedMemorySize,
                         STAGES * STAGE_BYTES);
    cudaFuncSetAttribute(gemm_mma<1>, cudaFuncAttributeMaxDynamicSharedMemorySize,
                         STAGES * STAGE_BYTES);

    __nv_bfloat16 *Xhi, *Xlo, *W1hi, *W1lo, *W2hi, *W2lo, *SAhi, *SAlo;
    cudaGetSymbolAddress((void**)&Xhi, g_Xhi);
    cudaGetSymbolAddress((void**)&Xlo, g_Xlo);
    cudaGetSymbolAddress((void**)&W1hi, g_W1hi);
    cudaGetSymbolAddress((void**)&W1lo, g_W1lo);
    cudaGetSymbolAddress((void**)&W2hi, g_W2hi);
    cudaGetSymbolAddress((void**)&W2lo, g_W2lo);
    cudaGetSymbolAddress((void**)&SAhi, g_SAhi);
    cudaGetSymbolAddress((void**)&SAlo, g_SAlo);
    float* SA;
    cudaGetSymbolAddress((void**)&SA, g_SA);

    init_kernel<<<1, 32>>>();
    cudaMemsetAsync(attn, 0, (size_t)BB * NH * SQ * KTOT * sizeof(float));

    // operand splits
    split_kernel<<<4096, 256>>>(X, Xhi, Xlo);
    splitT_kernel<<<dim3(96, 32), dim3(32, 8)>>>(W1, W1hi, W1lo, 1024, 3072);
    splitT_kernel<<<dim3(32, 32), dim3(32, 8)>>>(W2, W2hi, W2lo, 1024, 1024);

    // QKV projection (bf16x3 on tensor cores) + scatter
    gemm_mma<0><<<dim3(24, 32), 256, STAGES * STAGE_BYTES>>>(
        Xhi, Xlo, W1hi, W1lo, b1, out, pres);

    qnorm_kernel<<<8192, 256>>>();
    knorm_kernel<<<8192, 256>>>(past);
    knorm_kernel<<<8192, 256>>>(pres);
    cand_kernel<<<SQ, 256>>>(mask);

    attn_kernel<<<8192, 256>>>(past, pres, mask, attn);

    // output projection
    split_kernel<<<4096, 256>>>(SA, SAhi, SAlo);
    gemm_mma<1><<<dim3(8, 32), 256, STAGES * STAGE_BYTES>>>(
        SAhi, SAlo, W2hi, W2lo, b2, out, pres);
}